// round 15
// baseline (speedup 1.0000x reference)
#include <cuda_runtime.h>
#include <cuda_bf16.h>
#include <cstdint>

#define Cc   64
#define THWc 3136
#define Nn   6272
#define NTc  100352
#define BNT  200704
#define ZS   8

__device__ float g_F[6 * BNT];            // [qs,ks,vs,qt,kt,vt]
__device__ float g_Y[BNT];
__device__ float g_Sp[2 * 98 * 256];      // temporal score partials [b][chunk][t*16+s]
__device__ float g_Spart[ZS * 2 * 17 * Nn];   // [z][b][t(0..15)+L(16)][n]
__device__ uint32_t g_Qbf[2 * Nn * 8];    // [b][n][j]: bf16x2 {q'(t=2j), q'(2j+1)}, q'=0.25*log2e*q
__device__ uint32_t g_Kbf[2 * Nn * 8];    // [b][m][j]: bf16x2 {k(2j), k(2j+1)}
__device__ uint32_t g_Vbf[2 * 16 * (Nn / 2)]; // [b][t][mp]: bf16x2 {v(m=2mp), v(2mp+1)}

typedef unsigned long long u64;

// ---- f32x2 helpers ----
__device__ __forceinline__ float2 upk(u64 a) {
    float2 r; asm("mov.b64 {%0, %1}, %2;" : "=f"(r.x), "=f"(r.y) : "l"(a)); return r;
}
__device__ __forceinline__ u64 fma2(u64 a, u64 b, u64 c) {
    u64 d; asm("fma.rn.f32x2 %0, %1, %2, %3;" : "=l"(d) : "l"(a), "l"(b), "l"(c)); return d;
}
__device__ __forceinline__ u64 add2(u64 a, u64 b) {
    u64 d; asm("add.rn.f32x2 %0, %1, %2;" : "=l"(d) : "l"(a), "l"(b)); return d;
}
__device__ __forceinline__ float ex2f(float x) {
    float r; asm("ex2.approx.f32 %0, %1;" : "=f"(r) : "f"(x)); return r;
}
__device__ __forceinline__ uint32_t pkbf2(float lo, float hi) {
    uint32_t r;  // lower 16 bits = lo
    asm("cvt.rn.bf16x2.f32 %0, %1, %2;" : "=r"(r) : "f"(hi), "f"(lo));
    return r;
}
// mma.sync m16n8k16 bf16 (row.col), D += A*B
__device__ __forceinline__ void hmma(float4& d, const uint32_t* a, const uint32_t* bfr) {
    asm volatile(
        "mma.sync.aligned.m16n8k16.row.col.f32.bf16.bf16.f32 "
        "{%0,%1,%2,%3}, {%4,%5,%6,%7}, {%8,%9}, {%0,%1,%2,%3};"
        : "+f"(d.x), "+f"(d.y), "+f"(d.z), "+f"(d.w)
        : "r"(a[0]), "r"(a[1]), "r"(a[2]), "r"(a[3]), "r"(bfr[0]), "r"(bfr[1]));
}

// ---------------------------------------------------------------------------
// Six projections (R11-proven). grid 784 x 96.
// ---------------------------------------------------------------------------
__global__ void k_proj6(const float* __restrict__ x,
                        const float* __restrict__ W0, const float* __restrict__ b0,
                        const float* __restrict__ W1, const float* __restrict__ b1,
                        const float* __restrict__ W2, const float* __restrict__ b2,
                        const float* __restrict__ W3, const float* __restrict__ b3,
                        const float* __restrict__ W4, const float* __restrict__ b4,
                        const float* __restrict__ W5, const float* __restrict__ b5) {
    __shared__ float Wt[64][97];
    __shared__ __align__(16) float Xs[64][16];
    __shared__ float bs[96];

    const int tid  = threadIdx.x;
    const int grp  = (blockIdx.x >= 392) ? 1 : 0;
    const int pb   = blockIdx.x - grp * 392;
    const int b    = pb / 196;
    const int thw0 = (pb % 196) * 16;
    const int p3   = tid >> 5;
    const int ci   = tid & 31;
    const int P    = grp * 3 + p3;

    const float* W; const float* bias;
    switch (P) {
        case 0:  W = W0; bias = b0; break;
        case 1:  W = W1; bias = b1; break;
        case 2:  W = W2; bias = b2; break;
        case 3:  W = W3; bias = b3; break;
        case 4:  W = W4; bias = b4; break;
        default: W = W5; bias = b5; break;
    }
    {
        const float4* Wg = reinterpret_cast<const float4*>(W);
        #pragma unroll
        for (int it = 0; it < 16; ++it) {
            const int i = ci + it * 32;
            float4 w = Wg[i];
            const int r = i >> 4, c0 = (i & 15) * 4;
            Wt[c0 + 0][p3 * 32 + r] = w.x;
            Wt[c0 + 1][p3 * 32 + r] = w.y;
            Wt[c0 + 2][p3 * 32 + r] = w.z;
            Wt[c0 + 3][p3 * 32 + r] = w.w;
        }
    }
    bs[tid] = __ldg(&bias[ci]);

    const float4* xg = reinterpret_cast<const float4*>(x + (size_t)b * (Cc * THWc) + thw0);
    for (int i = tid; i < 256; i += 96) {
        int c = i >> 2, j = i & 3;
        reinterpret_cast<float4*>(&Xs[c][0])[j] = xg[c * (THWc / 4) + j];
    }
    __syncthreads();

    float acc[16];
    const float bv = bs[tid];
    #pragma unroll
    for (int p = 0; p < 16; ++p) acc[p] = bv;

    for (int c = 0; c < 64; ++c) {
        const float w = Wt[c][tid];
        #pragma unroll
        for (int j = 0; j < 4; ++j) {
            float4 xv = reinterpret_cast<const float4*>(&Xs[c][0])[j];
            acc[4 * j + 0] = fmaf(w, xv.x, acc[4 * j + 0]);
            acc[4 * j + 1] = fmaf(w, xv.y, acc[4 * j + 1]);
            acc[4 * j + 2] = fmaf(w, xv.z, acc[4 * j + 2]);
            acc[4 * j + 3] = fmaf(w, xv.w, acc[4 * j + 3]);
        }
    }
    float* dst = g_F + (size_t)P * BNT + (size_t)b * NTc + ci * THWc + thw0;
    #pragma unroll
    for (int j = 0; j < 4; ++j)
        reinterpret_cast<float4*>(dst)[j] =
            make_float4(acc[4 * j], acc[4 * j + 1], acc[4 * j + 2], acc[4 * j + 3]);
}

// ---------------------------------------------------------------------------
// bf16 staging. grid (49, 2) x 256. Q pre-scaled by 0.25*log2e.
// ---------------------------------------------------------------------------
__global__ void __launch_bounds__(256) k_prep() {
    const int tid = threadIdx.x, b = blockIdx.y, c0 = blockIdx.x * 128;
    const float QS = 0.25f * 1.4426950408889634f;

    if (tid < 128) {                       // Q transpose-gather
        const int n = c0 + tid;
        const float* Fq = g_F + 0 * BNT + (size_t)b * NTc;
        uint32_t r[8];
        #pragma unroll
        for (int j = 0; j < 8; ++j)
            r[j] = pkbf2(QS * Fq[(2 * j) * Nn + n], QS * Fq[(2 * j + 1) * Nn + n]);
        uint4* dst = reinterpret_cast<uint4*>(&g_Qbf[((size_t)b * Nn + n) * 8]);
        dst[0] = make_uint4(r[0], r[1], r[2], r[3]);
        dst[1] = make_uint4(r[4], r[5], r[6], r[7]);
    } else {                               // K transpose-gather
        const int m = c0 + tid - 128;
        const float* Fk = g_F + 1 * BNT + (size_t)b * NTc;
        uint32_t r[8];
        #pragma unroll
        for (int j = 0; j < 8; ++j)
            r[j] = pkbf2(Fk[(2 * j) * Nn + m], Fk[(2 * j + 1) * Nn + m]);
        uint4* dst = reinterpret_cast<uint4*>(&g_Kbf[((size_t)b * Nn + m) * 8]);
        dst[0] = make_uint4(r[0], r[1], r[2], r[3]);
        dst[1] = make_uint4(r[4], r[5], r[6], r[7]);
    }
    // V copy: 16 t x 128 m per block (all 256 threads)
    const int t = tid >> 4, seg = tid & 15;
    const float* Fv = g_F + 2 * BNT + (size_t)b * NTc + t * Nn + c0 + seg * 8;
    float4 a = reinterpret_cast<const float4*>(Fv)[0];
    float4 c = reinterpret_cast<const float4*>(Fv)[1];
    uint4 o;
    o.x = pkbf2(a.x, a.y); o.y = pkbf2(a.z, a.w);
    o.z = pkbf2(c.x, c.y); o.w = pkbf2(c.z, c.w);
    *reinterpret_cast<uint4*>(&g_Vbf[((size_t)(b * 16 + t)) * (Nn / 2) + ((c0 + seg * 8) >> 1)]) = o;
}

// ---------------------------------------------------------------------------
// Spatial flash attention on mma.sync (HMMA bf16), software-pipelined K/V
// fragment loads. grid (49, 2, ZS) x 128. Same math as R14 (proven).
// ---------------------------------------------------------------------------
__global__ void __launch_bounds__(128) k_sfmma() {
    const int tid  = threadIdx.x;
    const int w    = tid >> 5;
    const int lane = tid & 31;
    const int g    = lane >> 2;
    const int tig  = lane & 3;
    const int b    = blockIdx.y;
    const int z    = blockIdx.z;
    const int n0w  = blockIdx.x * 128 + w * 32;

    uint32_t A[2][4];
    #pragma unroll
    for (int qt = 0; qt < 2; ++qt) {
        const uint32_t* Qp = &g_Qbf[((size_t)b * Nn + n0w + 16 * qt) * 8];
        A[qt][0] = Qp[(size_t)g * 8 + tig];
        A[qt][1] = Qp[(size_t)(g + 8) * 8 + tig];
        A[qt][2] = Qp[(size_t)g * 8 + tig + 4];
        A[qt][3] = Qp[(size_t)(g + 8) * 8 + tig + 4];
    }

    float4 acc[2][2];
    #pragma unroll
    for (int i = 0; i < 2; ++i)
        #pragma unroll
        for (int j = 0; j < 2; ++j) acc[i][j] = make_float4(0.f, 0.f, 0.f, 0.f);
    float Llo[2] = {0.f, 0.f}, Lhi[2] = {0.f, 0.f};

    const uint32_t* Kb = &g_Kbf[(size_t)b * Nn * 8];
    const uint32_t* Vb = &g_Vbf[(size_t)b * 16 * (Nn / 2)];

    // fragment-load helper offsets (per-thread, m0-relative)
    const size_t kOff0 = (size_t)g * 8 + tig;
    const size_t kOff1 = (size_t)(8 + g) * 8 + tig;
    const size_t vRow0 = (size_t)g * (Nn / 2);
    const size_t vRow1 = (size_t)(8 + g) * (Nn / 2);

    uint32_t Kf[2][2], Vf[2][2];
    {   // preload chunk 0
        const int m0 = z * 49 * 16;
        Kf[0][0] = Kb[(size_t)m0 * 8 + kOff0];
        Kf[0][1] = Kb[(size_t)m0 * 8 + kOff0 + 4];
        Kf[1][0] = Kb[(size_t)m0 * 8 + kOff1];
        Kf[1][1] = Kb[(size_t)m0 * 8 + kOff1 + 4];
        Vf[0][0] = Vb[vRow0 + (m0 >> 1) + tig];
        Vf[0][1] = Vb[vRow0 + (m0 >> 1) + tig + 4];
        Vf[1][0] = Vb[vRow1 + (m0 >> 1) + tig];
        Vf[1][1] = Vb[vRow1 + (m0 >> 1) + tig + 4];
    }

    for (int i = 0; i < 49; ++i) {
        uint32_t Kn[2][2], Vn[2][2];
        if (i < 48) {                       // prefetch next chunk
            const int m1 = (z * 49 + i + 1) * 16;
            Kn[0][0] = Kb[(size_t)m1 * 8 + kOff0];
            Kn[0][1] = Kb[(size_t)m1 * 8 + kOff0 + 4];
            Kn[1][0] = Kb[(size_t)m1 * 8 + kOff1];
            Kn[1][1] = Kb[(size_t)m1 * 8 + kOff1 + 4];
            Vn[0][0] = Vb[vRow0 + (m1 >> 1) + tig];
            Vn[0][1] = Vb[vRow0 + (m1 >> 1) + tig + 4];
            Vn[1][0] = Vb[vRow1 + (m1 >> 1) + tig];
            Vn[1][1] = Vb[vRow1 + (m1 >> 1) + tig + 4];
        }

        #pragma unroll
        for (int qt = 0; qt < 2; ++qt) {
            float4 D0 = make_float4(0.f, 0.f, 0.f, 0.f);
            float4 D1 = make_float4(0.f, 0.f, 0.f, 0.f);
            hmma(D0, A[qt], Kf[0]);
            hmma(D1, A[qt], Kf[1]);

            float e00 = ex2f(D0.x), e01 = ex2f(D0.y);
            float e02 = ex2f(D0.z), e03 = ex2f(D0.w);
            float e10 = ex2f(D1.x), e11 = ex2f(D1.y);
            float e12 = ex2f(D1.z), e13 = ex2f(D1.w);
            Llo[qt] += (e00 + e01) + (e10 + e11);
            Lhi[qt] += (e02 + e03) + (e12 + e13);

            uint32_t Pf[4];
            Pf[0] = pkbf2(e00, e01);
            Pf[1] = pkbf2(e02, e03);
            Pf[2] = pkbf2(e10, e11);
            Pf[3] = pkbf2(e12, e13);

            hmma(acc[qt][0], Pf, Vf[0]);
            hmma(acc[qt][1], Pf, Vf[1]);
        }

        if (i < 48) {
            #pragma unroll
            for (int a2 = 0; a2 < 2; ++a2)
                #pragma unroll
                for (int b2 = 0; b2 < 2; ++b2) {
                    Kf[a2][b2] = Kn[a2][b2];
                    Vf[a2][b2] = Vn[a2][b2];
                }
        }
    }

    #pragma unroll
    for (int qt = 0; qt < 2; ++qt) {
        #pragma unroll
        for (int off = 1; off < 4; off <<= 1) {
            Llo[qt] += __shfl_xor_sync(0xffffffffu, Llo[qt], off);
            Lhi[qt] += __shfl_xor_sync(0xffffffffu, Lhi[qt], off);
        }
    }

    float* Pp = g_Spart + ((size_t)(z * 2 + b) * 17) * Nn;
    if (tig == 0) {
        #pragma unroll
        for (int qt = 0; qt < 2; ++qt) {
            Pp[16 * Nn + n0w + 16 * qt + g]     = Llo[qt];
            Pp[16 * Nn + n0w + 16 * qt + g + 8] = Lhi[qt];
        }
    }
    #pragma unroll
    for (int qt = 0; qt < 2; ++qt) {
        const int n = n0w + 16 * qt + g;
        #pragma unroll
        for (int tt = 0; tt < 2; ++tt) {
            const int t0 = 8 * tt + 2 * tig;
            Pp[(size_t)t0 * Nn + n]           = acc[qt][tt].x;
            Pp[(size_t)(t0 + 1) * Nn + n]     = acc[qt][tt].y;
            Pp[(size_t)t0 * Nn + n + 8]       = acc[qt][tt].z;
            Pp[(size_t)(t0 + 1) * Nn + n + 8] = acc[qt][tt].w;
        }
    }
}

// ---------------------------------------------------------------------------
// Spatial combine, t-split for parallelism: grid (49, 2, 4) x 128.
// Thread handles (b, n) x 4 t's; writes (=) at flat [t*Nn + n].
// ---------------------------------------------------------------------------
__global__ void __launch_bounds__(128) k_scomb() {
    const int tid = threadIdx.x;
    const int b   = blockIdx.y;
    const int tz  = blockIdx.z;
    const int n   = blockIdx.x * 128 + tid;

    float L = 0.f;
    #pragma unroll
    for (int z = 0; z < ZS; ++z)
        L += g_Spart[((size_t)(z * 2 + b) * 17 + 16) * Nn + n];
    const float inv = 1.f / L;

    float* Yb = g_Y + (size_t)b * NTc;
    #pragma unroll
    for (int tt = 0; tt < 4; ++tt) {
        const int t = tz * 4 + tt;
        float a = 0.f;
        #pragma unroll
        for (int z = 0; z < ZS; ++z)
            a += g_Spart[((size_t)(z * 2 + b) * 17 + t) * Nn + n];
        Yb[t * Nn + n] = a * inv;
    }
}

// ---------------------------------------------------------------------------
// Temporal score partials: grid (98, 2), 64 n per block (2x parallelism).
// ---------------------------------------------------------------------------
__global__ void __launch_bounds__(256) k_tempS() {
    __shared__ __align__(16) float Qs[16][68];
    __shared__ __align__(16) float Ks2[16][68];

    const int tid = threadIdx.x, b = blockIdx.y, n0 = blockIdx.x * 64;
    const float* Q = g_F + 3 * BNT + (size_t)b * NTc + (size_t)n0 * 16;
    const float* K = g_F + 4 * BNT + (size_t)b * NTc + (size_t)n0 * 16;

    {   // 256 float4 per tensor, 1 per thread; transpose [n][16] -> [t][n]
        const int n = tid >> 2, t0 = (tid & 3) * 4;
        float4 qv = reinterpret_cast<const float4*>(Q)[tid];
        Qs[t0 + 0][n] = qv.x; Qs[t0 + 1][n] = qv.y;
        Qs[t0 + 2][n] = qv.z; Qs[t0 + 3][n] = qv.w;
        float4 kv = reinterpret_cast<const float4*>(K)[tid];
        Ks2[t0 + 0][n] = kv.x; Ks2[t0 + 1][n] = kv.y;
        Ks2[t0 + 2][n] = kv.z; Ks2[t0 + 3][n] = kv.w;
    }
    __syncthreads();

    const int t = tid >> 4, s = tid & 15;
    u64 sa = 0ULL, sb = 0ULL, sc = 0ULL, sd = 0ULL;
    #pragma unroll
    for (int j = 0; j < 16; j += 2) {
        ulonglong2 q4 = *reinterpret_cast<const ulonglong2*>(&Qs[t][4 * j]);
        ulonglong2 k4 = *reinterpret_cast<const ulonglong2*>(&Ks2[s][4 * j]);
        sa = fma2(q4.x, k4.x, sa); sb = fma2(q4.y, k4.y, sb);
        ulonglong2 q5 = *reinterpret_cast<const ulonglong2*>(&Qs[t][4 * j + 4]);
        ulonglong2 k5 = *reinterpret_cast<const ulonglong2*>(&Ks2[s][4 * j + 4]);
        sc = fma2(q5.x, k5.x, sc); sd = fma2(q5.y, k5.y, sd);
    }
    float2 r = upk(add2(add2(sa, sb), add2(sc, sd)));
    g_Sp[((size_t)b * 98 + blockIdx.x) * 256 + tid] = r.x + r.y;
}

// ---------------------------------------------------------------------------
// Temporal apply with FUSED softmax (replaces k_tsoft): each block first
// reduces the 98 score chunks and computes softmax into smem (identical
// arithmetic order to the old k_tsoft), then applies. grid 98 x 256,
// += at flat [n*16 + t], AFTER k_scomb.
// ---------------------------------------------------------------------------
__global__ void __launch_bounds__(256) k_tapply() {
    __shared__ float sA[512];
    const int tid = threadIdx.x;

    // --- fused softmax: entries (b=0, ts=tid) and (b=1, ts=tid) ---
    {
        float a0 = 0.f, a1 = 0.f;
        #pragma unroll 7
        for (int c = 0; c < 98; ++c) {
            a0 += g_Sp[(size_t)c * 256 + tid];
            a1 += g_Sp[(size_t)(98 + c) * 256 + tid];
        }
        float m0 = a0, m1 = a1;
        #pragma unroll
        for (int off = 1; off < 16; off <<= 1) {
            m0 = fmaxf(m0, __shfl_xor_sync(0xffffffffu, m0, off));
            m1 = fmaxf(m1, __shfl_xor_sync(0xffffffffu, m1, off));
        }
        float e0 = __expf(0.25f * (a0 - m0));
        float e1 = __expf(0.25f * (a1 - m1));
        float s0 = e0, s1 = e1;
        #pragma unroll
        for (int off = 1; off < 16; off <<= 1) {
            s0 += __shfl_xor_sync(0xffffffffu, s0, off);
            s1 += __shfl_xor_sync(0xffffffffu, s1, off);
        }
        sA[tid]       = e0 / s0;
        sA[tid + 256] = e1 / s1;
    }
    __syncthreads();

    const int idx2 = blockIdx.x * 256 + tid;
    const int ng = idx2 >> 1, half = idx2 & 1;
    const int b = ng / Nn, n = ng - b * Nn;
    const float4* vp = reinterpret_cast<const float4*>(g_F + 5 * BNT + (size_t)b * NTc + n * 16);
    float v[16];
    #pragma unroll
    for (int j = 0; j < 4; ++j) {
        float4 v4 = vp[j];
        v[4 * j] = v4.x; v[4 * j + 1] = v4.y; v[4 * j + 2] = v4.z; v[4 * j + 3] = v4.w;
    }
    const float* A = &sA[b * 256];
    float4* yp = reinterpret_cast<float4*>(g_Y + (size_t)b * NTc + n * 16);
    #pragma unroll
    for (int jj = 0; jj < 2; ++jj) {
        const int j = half * 2 + jj;
        float4 y4 = yp[j];
        float o[4];
        #pragma unroll
        for (int k = 0; k < 4; ++k) {
            const int t = 4 * j + k;
            float a = 0.f;
            #pragma unroll
            for (int s = 0; s < 16; ++s) a = fmaf(A[t * 16 + s], v[s], a);
            o[k] = a;
        }
        y4.x += o[0]; y4.y += o[1]; y4.z += o[2]; y4.w += o[3];
        yp[j] = y4;
    }
}

__global__ void __launch_bounds__(64) k_out(const float* __restrict__ x,
                                            const float* __restrict__ Ww,
                                            const float* __restrict__ bw,
                                            float* __restrict__ out) {
    __shared__ float Wt[32][65];
    __shared__ __align__(16) float Ys[32][8];
    const int tid = threadIdx.x, pb = blockIdx.x;
    const int b = pb / 392, thw0 = (pb % 392) * 8;
    {
        const float4* Wg = reinterpret_cast<const float4*>(Ww);
        #pragma unroll
        for (int k = 0; k < 8; ++k) {
            const int i = tid + k * 64;
            float4 w = Wg[i];
            const int o = i >> 3, c0 = (i & 7) * 4;
            Wt[c0 + 0][o] = w.x; Wt[c0 + 1][o] = w.y;
            Wt[c0 + 2][o] = w.z; Wt[c0 + 3][o] = w.w;
        }
    }
    const float* Yb = g_Y + (size_t)b * NTc + thw0;
    {
        const int ci = tid >> 1, j = tid & 1;
        reinterpret_cast<float4*>(&Ys[ci][0])[j] =
            reinterpret_cast<const float4*>(Yb + ci * THWc)[j];
    }
    __syncthreads();
    float acc[8];
    const float bv = __ldg(&bw[tid]);
    #pragma unroll
    for (int p = 0; p < 8; ++p) acc[p] = bv;
    #pragma unroll 8
    for (int ci = 0; ci < 32; ++ci) {
        const float w = Wt[ci][tid];
        #pragma unroll
        for (int j = 0; j < 2; ++j) {
            float4 yv = reinterpret_cast<const float4*>(&Ys[ci][0])[j];
            acc[4 * j + 0] = fmaf(w, yv.x, acc[4 * j + 0]);
            acc[4 * j + 1] = fmaf(w, yv.y, acc[4 * j + 1]);
            acc[4 * j + 2] = fmaf(w, yv.z, acc[4 * j + 2]);
            acc[4 * j + 3] = fmaf(w, yv.w, acc[4 * j + 3]);
        }
    }
    const size_t off = (size_t)b * (Cc * THWc) + (size_t)tid * THWc + thw0;
    const float4* xg = reinterpret_cast<const float4*>(x + off);
    float4* og = reinterpret_cast<float4*>(out + off);
    #pragma unroll
    for (int j = 0; j < 2; ++j) {
        float4 xv = xg[j];
        og[j] = make_float4(acc[4 * j + 0] + xv.x, acc[4 * j + 1] + xv.y,
                            acc[4 * j + 2] + xv.z, acc[4 * j + 3] + xv.w);
    }
}

// ---------------------------------------------------------------------------
extern "C" void kernel_launch(void* const* d_in, const int* in_sizes, int n_in,
                              void* d_out, int out_size) {
    (void)in_sizes; (void)n_in; (void)out_size;
    const float* x   = (const float*)d_in[0];
    const float* Wqs = (const float*)d_in[1];  const float* bqs = (const float*)d_in[2];
    const float* Wks = (const float*)d_in[3];  const float* bks = (const float*)d_in[4];
    const float* Wvs = (const float*)d_in[5];  const float* bvs = (const float*)d_in[6];
    const float* Wqt = (const float*)d_in[7];  const float* bqt = (const float*)d_in[8];
    const float* Wkt = (const float*)d_in[9];  const float* bkt = (const float*)d_in[10];
    const float* Wvt = (const float*)d_in[11]; const float* bvt = (const float*)d_in[12];
    const float* Ww  = (const float*)d_in[13]; const float* bw  = (const float*)d_in[14];
    float* out = (float*)d_out;

    k_proj6<<<784, 96>>>(x, Wqs, bqs, Wks, bks, Wvs, bvs,
                            Wqt, bqt, Wkt, bkt, Wvt, bvt);
    k_prep<<<dim3(49, 2), 256>>>();
    k_sfmma<<<dim3(49, 2, ZS), 128>>>();
    k_tempS<<<dim3(98, 2), 256>>>();
    k_scomb<<<dim3(49, 2, 4), 128>>>();
    k_tapply<<<98, 256>>>();
    k_out<<<784, 64>>>(x, Ww, bw, out);
}